// round 9
// baseline (speedup 1.0000x reference)
#include <cuda_runtime.h>
#include <cuda_bf16.h>
#include <math.h>
#include <stdint.h>

#define T_STEPS 512
#define BATCH   16
#define DIM     4096
#define S_TOT   (T_STEPS * BATCH)   // 8192
#define BD      (BATCH * DIM)       // 65536
#define RCTA    128                  // recurrence CTAs (2 per monarch block)

// Gate GEMM dims: [GM, GK] x [GN, GK]^T -> [GM, GN]
#define GM 8192
#define GN 4096
#define GK 4096
#define BK 64
#define NCHUNK (GK / BK)            // 64

// Scratch (device globals; no runtime allocation allowed)
__device__ float g_zx[(size_t)S_TOT * DIM];
__device__ float g_mx[(size_t)S_TOT * DIM];
__device__ float g_zbuf[2 * BD];
__device__ unsigned g_count = 0;
__device__ unsigned g_gen   = 0;
// bf16 split operands for the tensor-core gate GEMM
__device__ uint16_t g_Ahi[(size_t)GM * GK];
__device__ uint16_t g_Alo[(size_t)GM * GK];
__device__ uint16_t g_Bhi[(size_t)GN * GK];
__device__ uint16_t g_Blo[(size_t)GN * GK];

// ---------------------------------------------------------------------------
// PTX helpers (base-target instructions only: valid at compute_103)
// ---------------------------------------------------------------------------
__device__ __forceinline__ uint32_t smem_u32(const void* p) {
    uint32_t a;
    asm("{ .reg .u64 t; cvta.to.shared.u64 t, %1; cvt.u32.u64 %0, t; }"
        : "=r"(a) : "l"(p));
    return a;
}
__device__ __forceinline__ void cp_async16(uint32_t dst, const void* src) {
    asm volatile("cp.async.cg.shared.global [%0], [%1], 16;" :: "r"(dst), "l"(src));
}
#define CP_COMMIT() asm volatile("cp.async.commit_group;" ::: "memory")
#define CP_WAIT2()  asm volatile("cp.async.wait_group 2;" ::: "memory")
#define CP_WAIT1()  asm volatile("cp.async.wait_group 1;" ::: "memory")
#define CP_WAIT0()  asm volatile("cp.async.wait_group 0;" ::: "memory")

__device__ __forceinline__ void ldsm_x4(uint32_t* r, uint32_t addr) {
    asm volatile("ldmatrix.sync.aligned.m8n8.x4.shared.b16 {%0,%1,%2,%3}, [%4];"
                 : "=r"(r[0]), "=r"(r[1]), "=r"(r[2]), "=r"(r[3]) : "r"(addr));
}
__device__ __forceinline__ void mma_bf16(float* d, const uint32_t* a,
                                         uint32_t b0, uint32_t b1) {
    asm volatile(
        "mma.sync.aligned.m16n8k16.row.col.f32.bf16.bf16.f32 "
        "{%0,%1,%2,%3}, {%4,%5,%6,%7}, {%8,%9}, {%0,%1,%2,%3};"
        : "+f"(d[0]), "+f"(d[1]), "+f"(d[2]), "+f"(d[3])
        : "r"(a[0]), "r"(a[1]), "r"(a[2]), "r"(a[3]), "r"(b0), "r"(b1));
}

// ---------------------------------------------------------------------------
// fp32 -> bf16 (hi, lo) split, 8 elems/thread
// ---------------------------------------------------------------------------
__global__ __launch_bounds__(256) void split_kernel(
    const float* __restrict__ src, uint16_t* __restrict__ hi,
    uint16_t* __restrict__ lo, int n8)
{
    int i = blockIdx.x * blockDim.x + threadIdx.x;
    if (i >= n8) return;
    const float4* s4 = (const float4*)src;
    float4 a = s4[2 * i], b = s4[2 * i + 1];
    float v[8] = {a.x, a.y, a.z, a.w, b.x, b.y, b.z, b.w};
    uint32_t Hp[4], Lp[4];
    #pragma unroll
    for (int q = 0; q < 4; q++) {
        __nv_bfloat16 h0 = __float2bfloat16_rn(v[2 * q]);
        __nv_bfloat16 h1 = __float2bfloat16_rn(v[2 * q + 1]);
        float r0 = v[2 * q]     - __bfloat162float(h0);
        float r1 = v[2 * q + 1] - __bfloat162float(h1);
        __nv_bfloat16 l0 = __float2bfloat16_rn(r0);
        __nv_bfloat16 l1 = __float2bfloat16_rn(r1);
        Hp[q] = (uint32_t)__bfloat16_as_ushort(h0) | ((uint32_t)__bfloat16_as_ushort(h1) << 16);
        Lp[q] = (uint32_t)__bfloat16_as_ushort(l0) | ((uint32_t)__bfloat16_as_ushort(l1) << 16);
    }
    *(uint4*)(hi + 8 * (size_t)i) = make_uint4(Hp[0], Hp[1], Hp[2], Hp[3]);
    *(uint4*)(lo + 8 * (size_t)i) = make_uint4(Lp[0], Lp[1], Lp[2], Lp[3]);
}

// ---------------------------------------------------------------------------
// Tensor-core gate GEMM via mma.sync (bf16, 3-term split, fp32 accum).
// Tile 128x128x64, 256 threads, 3-stage cp.async pipeline, SW128 smem.
// MMA issue order is TERM-OUTERMOST so same-accumulator MMAs are 16 apart
// (RAW latency fully hidden), instead of 3 back-to-back dependent MMAs.
// ---------------------------------------------------------------------------
#define STG_SZ   65536
#define OFF_ALO  16384
#define OFF_BHI  32768
#define OFF_BLO  49152

__device__ __forceinline__ void load_stage(uint32_t sb, int m0, int n0, size_t kof)
{
    const int tid = threadIdx.x;
    #pragma unroll
    for (int i = 0; i < 4; i++) {
        int idx = tid + 256 * i;
        int row = idx >> 3, ch = idx & 7;
        uint32_t sw = (uint32_t)((row * 128 + ch * 16) ^ ((row & 7) << 4));
        size_t ga = (size_t)(m0 + row) * GK + kof + ch * 8;
        size_t gb = (size_t)(n0 + row) * GK + kof + ch * 8;
        cp_async16(sb + sw,           g_Ahi + ga);
        cp_async16(sb + OFF_ALO + sw, g_Alo + ga);
        cp_async16(sb + OFF_BHI + sw, g_Bhi + gb);
        cp_async16(sb + OFF_BLO + sw, g_Blo + gb);
    }
}

__global__ __launch_bounds__(256, 1) void gate_mma_kernel(
    const float* __restrict__ bg, float* __restrict__ out)
{
    extern __shared__ char smem[];
    const uint32_t sbase = smem_u32(smem);

    const int tid  = threadIdx.x;
    const int lane = tid & 31;
    const int wid  = tid >> 5;
    const int wm   = wid & 3;          // warp m index (0-3) -> m offset wm*32
    const int wn   = wid >> 2;         // warp n index (0-1) -> n offset wn*64
    const int n0   = blockIdx.x * 128; // n fastest for L2 reuse of B
    const int m0   = blockIdx.y * 128;

    // per-lane ldmatrix address components (row&7 == lane&7 for all fragments)
    const uint32_t xorv = (uint32_t)((lane & 7) << 4);
    const uint32_t hi16 = (uint32_t)((lane >> 4) * 16);
    const uint32_t aRow = (uint32_t)((wm * 32 + (lane & 15)) * 128);
    const uint32_t bRow = (uint32_t)((wn * 64 + (lane & 15)) * 128);

    float d[2][8][4];
    #pragma unroll
    for (int mf = 0; mf < 2; mf++)
        #pragma unroll
        for (int nf = 0; nf < 8; nf++)
            #pragma unroll
            for (int q = 0; q < 4; q++) d[mf][nf][q] = 0.0f;

    load_stage(sbase,              m0, n0, 0);
    CP_COMMIT();
    load_stage(sbase + STG_SZ,     m0, n0, BK);
    CP_COMMIT();

    uint32_t bufoff[3] = {0u, (uint32_t)STG_SZ, 2u * (uint32_t)STG_SZ};

    for (int c = 0; c < NCHUNK; c++) {
        if (c + 2 < NCHUNK) {
            load_stage(sbase + bufoff[(c + 2) % 3], m0, n0, (size_t)(c + 2) * BK);
            CP_COMMIT();
            CP_WAIT2();
        } else if (c + 1 < NCHUNK) {
            CP_WAIT1();
        } else {
            CP_WAIT0();
        }
        __syncthreads();

        const uint32_t sb = sbase + bufoff[c % 3];
        #pragma unroll
        for (int s = 0; s < 4; s++) {
            const uint32_t cb = ((uint32_t)(s * 32) + hi16) ^ xorv;
            uint32_t ah[2][4], al[2][4], bh[4][4], bl[4][4];
            ldsm_x4(ah[0], sb + aRow + cb);
            ldsm_x4(ah[1], sb + aRow + 2048 + cb);
            ldsm_x4(al[0], sb + OFF_ALO + aRow + cb);
            ldsm_x4(al[1], sb + OFF_ALO + aRow + 2048 + cb);
            #pragma unroll
            for (int g = 0; g < 4; g++) {
                ldsm_x4(bh[g], sb + OFF_BHI + bRow + g * 2048 + cb);
                ldsm_x4(bl[g], sb + OFF_BLO + bRow + g * 2048 + cb);
            }
            // B x4 reg mapping: nf even -> {r0, r2}, nf odd -> {r1, r3}
            // TERM-OUTERMOST: 16 independent accumulators between reuses of
            // the same d -> MMA RAW latency hidden by issue of the other 15.
            #pragma unroll
            for (int mf = 0; mf < 2; mf++)
                #pragma unroll
                for (int nf = 0; nf < 8; nf++) {
                    const int g = nf >> 1, o = nf & 1;
                    mma_bf16(d[mf][nf], ah[mf], bh[g][o], bh[g][o + 2]);
                }
            #pragma unroll
            for (int mf = 0; mf < 2; mf++)
                #pragma unroll
                for (int nf = 0; nf < 8; nf++) {
                    const int g = nf >> 1, o = nf & 1;
                    mma_bf16(d[mf][nf], ah[mf], bl[g][o], bl[g][o + 2]);
                }
            #pragma unroll
            for (int mf = 0; mf < 2; mf++)
                #pragma unroll
                for (int nf = 0; nf < 8; nf++) {
                    const int g = nf >> 1, o = nf & 1;
                    mma_bf16(d[mf][nf], al[mf], bh[g][o], bh[g][o + 2]);
                }
        }
        __syncthreads();
    }

    // epilogue: bias + silu straight from fragments
    const int erow  = lane >> 2;
    const int ecol0 = (lane & 3) * 2;
    #pragma unroll
    for (int nf = 0; nf < 8; nf++) {
        const int col = n0 + wn * 64 + nf * 8 + ecol0;
        const float2 bgv = *(const float2*)(bg + col);
        #pragma unroll
        for (int mf = 0; mf < 2; mf++) {
            const int row = m0 + wm * 32 + mf * 16 + erow;
            float v0 = d[mf][nf][0] + bgv.x;
            float v1 = d[mf][nf][1] + bgv.y;
            float2 r0 = make_float2(v0 / (1.0f + expf(-v0)), v1 / (1.0f + expf(-v1)));
            *(float2*)(out + (size_t)row * GN + col) = r0;
            float v2 = d[mf][nf][2] + bgv.x;
            float v3 = d[mf][nf][3] + bgv.y;
            float2 r1 = make_float2(v2 / (1.0f + expf(-v2)), v3 / (1.0f + expf(-v3)));
            *(float2*)(out + (size_t)(row + 8) * GN + col) = r1;
        }
    }
}

// ---------------------------------------------------------------------------
// Monarch stage 1 over all samples: zx[s,k,i] = sum_j B1[k,i,j] * x[s, k*64+j]
// ---------------------------------------------------------------------------
__global__ __launch_bounds__(256) void monarch_s1_kernel(
    const float* __restrict__ B1, const float* __restrict__ vin)
{
    __shared__ float wT[64 * 68];
    __shared__ float xs[64 * 68];

    const int k  = blockIdx.x;
    const int s0 = blockIdx.y * 64;
    const int t  = threadIdx.x;
    const float* w = B1 + (size_t)k * 4096;

    #pragma unroll
    for (int r = 0; r < 16; r++) {
        int idx = t + 256 * r;
        int i = idx >> 6, j = idx & 63;
        wT[j * 68 + i] = w[idx];
    }
    {
        int sr = t >> 4, j4 = (t & 15) * 4;
        #pragma unroll
        for (int it = 0; it < 4; it++) {
            int s = sr + it * 16;
            float4 v = *(const float4*)(vin + (size_t)(s0 + s) * DIM + k * 64 + j4);
            *(float4*)(xs + s * 68 + j4) = v;
        }
    }
    __syncthreads();

    const int i0 = (t & 15) * 4;
    const int sg = t >> 4;
    float acc[4][4] = {};
    #pragma unroll 4
    for (int j = 0; j < 64; j++) {
        float4 w4 = *(const float4*)&wT[j * 68 + i0];
        #pragma unroll
        for (int q = 0; q < 4; q++) {
            float hv = xs[(sg * 4 + q) * 68 + j];
            acc[q][0] += w4.x * hv; acc[q][1] += w4.y * hv;
            acc[q][2] += w4.z * hv; acc[q][3] += w4.w * hv;
        }
    }
    #pragma unroll
    for (int q = 0; q < 4; q++) {
        int s = sg * 4 + q;
        *(float4*)(g_zx + (size_t)(s0 + s) * DIM + k * 64 + i0) =
            make_float4(acc[q][0], acc[q][1], acc[q][2], acc[q][3]);
    }
}

// ---------------------------------------------------------------------------
// Monarch stage 2: Mx[s, a*64+i] = sum_j B2[a,i,j] * zx[s, j*64 + a]
// ---------------------------------------------------------------------------
__global__ __launch_bounds__(256) void monarch_s2_kernel(
    const float* __restrict__ B2)
{
    __shared__ float wT[64 * 68];
    __shared__ float zs[64 * 68];

    const int a  = blockIdx.x;
    const int s0 = blockIdx.y * 64;
    const int t  = threadIdx.x;
    const float* w = B2 + (size_t)a * 4096;

    #pragma unroll
    for (int r = 0; r < 16; r++) {
        int idx = t + 256 * r;
        int i = idx >> 6, j = idx & 63;
        wT[j * 68 + i] = w[idx];
    }
    #pragma unroll
    for (int r = 0; r < 16; r++) {
        int idx = t + 256 * r;
        int s = idx >> 6, j = idx & 63;
        zs[s * 68 + j] = g_zx[(size_t)(s0 + s) * DIM + j * 64 + a];
    }
    __syncthreads();

    const int i0 = (t & 15) * 4;
    const int sg = t >> 4;
    float acc[4][4] = {};
    #pragma unroll 4
    for (int j = 0; j < 64; j++) {
        float4 w4 = *(const float4*)&wT[j * 68 + i0];
        #pragma unroll
        for (int q = 0; q < 4; q++) {
            float hv = zs[(sg * 4 + q) * 68 + j];
            acc[q][0] += w4.x * hv; acc[q][1] += w4.y * hv;
            acc[q][2] += w4.z * hv; acc[q][3] += w4.w * hv;
        }
    }
    #pragma unroll
    for (int q = 0; q < 4; q++) {
        int s = sg * 4 + q;
        *(float4*)(g_mx + (size_t)(s0 + s) * DIM + a * 64 + i0) =
            make_float4(acc[q][0], acc[q][1], acc[q][2], acc[q][3]);
    }
}

// ---------------------------------------------------------------------------
// Grid-wide sense barrier (release/acquire through L2). RCTA co-resident CTAs.
// ---------------------------------------------------------------------------
__device__ __forceinline__ void grid_barrier(unsigned target)
{
    __syncthreads();
    if (threadIdx.x == 0) {
        unsigned prev;
        asm volatile("atom.acq_rel.gpu.add.u32 %0, [%1], %2;"
                     : "=r"(prev) : "l"(&g_count), "r"(1u) : "memory");
        if (prev == RCTA - 1) {
            asm volatile("st.relaxed.gpu.u32 [%0], %1;" :: "l"(&g_count), "r"(0u) : "memory");
            asm volatile("red.release.gpu.add.u32 [%0], %1;" :: "l"(&g_gen), "r"(1u) : "memory");
        } else {
            unsigned v;
            do {
                asm volatile("ld.acquire.gpu.u32 %0, [%1];" : "=r"(v) : "l"(&g_gen) : "memory");
            } while ((int)(v - target) < 0);
        }
    }
    __syncthreads();
}

// ---------------------------------------------------------------------------
// Persistent recurrence kernel, 128 CTAs: CTA (c, half) owns monarch block c
// for batch rows [half*8, half*8+8). The all-to-all z shuffle stays within a
// half. FMA work spreads over 128 SMs.
// ---------------------------------------------------------------------------
__global__ __launch_bounds__(256) void recurrence_kernel(
    const float* __restrict__ B1, const float* __restrict__ B2,
    const float* __restrict__ h0, const float* __restrict__ bvec,
    float* __restrict__ out, float* __restrict__ hbuf)
{
    __shared__ float wT1[64 * 68];   // wT1[j*68+i] = B1[c][i][j]
    __shared__ float wT2[64 * 68];
    __shared__ float hs[8 * 68];     // h[b_local, c*64 + j]
    __shared__ float zs[8 * 68];     // z[b_local, j*64 + c]
    __shared__ unsigned s_base;

    const int c    = blockIdx.x & 63;
    const int half = blockIdx.x >> 6;
    const int tid  = threadIdx.x;
    const int bl   = tid >> 5;          // 0..7 local batch
    const int bgl  = half * 8 + bl;     // global batch row
    const int i0   = (tid & 31) * 2;    // 0..62

    if (tid == 0) {
        unsigned v;
        asm volatile("ld.acquire.gpu.u32 %0, [%1];" : "=r"(v) : "l"(&g_gen) : "memory");
        s_base = v;
    }

    #pragma unroll
    for (int r = 0; r < 16; r++) {
        int idx = tid + 256 * r;
        int i = idx >> 6, j = idx & 63;
        wT1[j * 68 + i] = B1[(size_t)c * 4096 + idx];
        wT2[j * 68 + i] = B2[(size_t)c * 4096 + idx];
    }
    {
        float2 v = *(const float2*)(h0 + (size_t)bgl * DIM + c * 64 + i0);
        *(float2*)&hs[bl * 68 + i0] = v;
        *(float2*)(hbuf + (size_t)bgl * DIM + c * 64 + i0) = v;   // h[0] output
    }
    const float2 bb = *(const float2*)(bvec + c * 64 + i0);
    __syncthreads();
    const unsigned base = s_base;

    for (int t = 0; t < T_STEPS; t++) {
        // ---- stage 1: z[b, c, i] = sum_j W1[c][i][j] * h[b, c*64+j] ----
        float ax = 0.f, ay = 0.f;
        #pragma unroll 8
        for (int j = 0; j < 64; j++) {
            float2 w2 = *(const float2*)&wT1[j * 68 + i0];
            float hv = hs[bl * 68 + j];
            ax += w2.x * hv; ay += w2.y * hv;
        }
        float* zb = g_zbuf + (size_t)(t & 1) * BD;
        *(float2*)(zb + (size_t)bgl * DIM + c * 64 + i0) = make_float2(ax, ay);

        grid_barrier(base + (unsigned)t + 1u);

        // ---- gather shuffled z: zs[b2][j] = z[half*8+b2, j*64 + c] ----
        #pragma unroll
        for (int r = 0; r < 2; r++) {
            int idx = tid + 256 * r;
            int b2 = idx >> 6, j = idx & 63;
            zs[b2 * 68 + j] = zb[(size_t)(half * 8 + b2) * DIM + j * 64 + c];
        }
        __syncthreads();

        // ---- stage 2 + tanh + gating ----
        float cx = 0.f, cy = 0.f;
        #pragma unroll 8
        for (int j = 0; j < 64; j++) {
            float2 w2 = *(const float2*)&wT2[j * 68 + i0];
            float zv = zs[bl * 68 + j];
            cx += w2.x * zv; cy += w2.y * zv;
        }

        const size_t base_idx = (size_t)bgl * DIM + c * 64 + i0;
        float2 mx2 = *(const float2*)(g_mx + (size_t)t * BD + base_idx);
        float2 gg  = *(const float2*)(out + (size_t)t * BD + base_idx);  // gate

        float h0v = tanhf(cx + mx2.x + bb.x);
        float h1v = tanhf(cy + mx2.y + bb.y);

        *(float2*)(hbuf + (size_t)(t + 1) * BD + base_idx) = make_float2(h0v, h1v);
        *(float2*)(out + (size_t)t * BD + base_idx) =
            make_float2(h0v * gg.x, h1v * gg.y);

        // update local h slice for next step's stage 1 (safe: all stage-1 reads
        // of hs finished before the grid barrier above)
        *(float2*)&hs[bl * 68 + i0] = make_float2(h0v, h1v);
        __syncthreads();
    }
}

// ---------------------------------------------------------------------------
// Inputs (metadata order): x, h0, B1_h, B2_h, B1_x, B2_x, W_gate, b, b_gate
// Output: [ output (T,B,D) | h (T+1,B,D) ] float32
// ---------------------------------------------------------------------------
extern "C" void kernel_launch(void* const* d_in, const int* in_sizes, int n_in,
                              void* d_out, int out_size)
{
    const float* x    = (const float*)d_in[0];
    const float* h0   = (const float*)d_in[1];
    const float* B1h  = (const float*)d_in[2];
    const float* B2h  = (const float*)d_in[3];
    const float* B1x  = (const float*)d_in[4];
    const float* B2x  = (const float*)d_in[5];
    const float* Wg   = (const float*)d_in[6];
    const float* bvec = (const float*)d_in[7];
    const float* bg   = (const float*)d_in[8];

    float* out  = (float*)d_out;                       // [T, B, D]
    float* hbuf = out + (size_t)T_STEPS * BD;          // [T+1, B, D]

    uint16_t *pAhi, *pAlo, *pBhi, *pBlo;
    cudaGetSymbolAddress((void**)&pAhi, g_Ahi);
    cudaGetSymbolAddress((void**)&pAlo, g_Alo);
    cudaGetSymbolAddress((void**)&pBhi, g_Bhi);
    cudaGetSymbolAddress((void**)&pBlo, g_Blo);

    // bf16 split of x and W_gate
    split_kernel<<<(GM * (GK / 8)) / 256, 256>>>(x, pAhi, pAlo, GM * GK / 8);
    split_kernel<<<(GN * (GK / 8)) / 256, 256>>>(Wg, pBhi, pBlo, GN * GK / 8);

    // tensor-core gate GEMM (mma.sync) -> gate stored into output region
    static const int SMEM_SZ = 3 * STG_SZ;   // 192 KB
    cudaFuncSetAttribute(gate_mma_kernel, cudaFuncAttributeMaxDynamicSharedMemorySize, SMEM_SZ);
    gate_mma_kernel<<<dim3(GN / 128, GM / 128), 256, SMEM_SZ>>>(bg, out);

    // Mx = monarch(B1_x, B2_x, x) for all timesteps
    monarch_s1_kernel<<<dim3(64, S_TOT / 64), 256>>>(B1x, x);
    monarch_s2_kernel<<<dim3(64, S_TOT / 64), 256>>>(B2x);

    // Entire 512-step recurrence in ONE persistent kernel (128 CTAs)
    recurrence_kernel<<<RCTA, 256>>>(B1h, B2h, h0, bvec, out, hbuf);
}

// round 13
// speedup vs baseline: 2.1014x; 2.1014x over previous
#include <cuda_runtime.h>
#include <cuda_fp16.h>
#include <math.h>
#include <stdint.h>

#define T_STEPS 512
#define BATCH   16
#define DIM     4096
#define S_TOT   (T_STEPS * BATCH)   // 8192
#define BD      (BATCH * DIM)       // 65536
#define RCTA    128                  // recurrence CTAs (2 per monarch block)

// Gate GEMM dims: [GM, GK] x [GN, GK]^T -> [GM, GN]
#define GM 8192
#define GN 4096
#define GK 4096
#define BK 64
#define NCHUNK (GK / BK)            // 64

// Scratch (device globals; no runtime allocation allowed)
__device__ float g_zx[(size_t)S_TOT * DIM];
__device__ float g_mx[(size_t)S_TOT * DIM];
__device__ float g_zbuf[2 * BD];
__device__ unsigned g_count = 0;
__device__ unsigned g_gen   = 0;
// fp16 operands for the tensor-core gate GEMM (single term; error ~2^-12
// per product -> global rel_err ~2e-4 << 1e-3 threshold)
__device__ uint16_t g_A16[(size_t)GM * GK];
__device__ uint16_t g_B16[(size_t)GN * GK];

// ---------------------------------------------------------------------------
// PTX helpers (base-target instructions only: valid at compute_103)
// ---------------------------------------------------------------------------
__device__ __forceinline__ uint32_t smem_u32(const void* p) {
    uint32_t a;
    asm("{ .reg .u64 t; cvta.to.shared.u64 t, %1; cvt.u32.u64 %0, t; }"
        : "=r"(a) : "l"(p));
    return a;
}
__device__ __forceinline__ void cp_async16(uint32_t dst, const void* src) {
    asm volatile("cp.async.cg.shared.global [%0], [%1], 16;" :: "r"(dst), "l"(src));
}
#define CP_COMMIT() asm volatile("cp.async.commit_group;" ::: "memory")
#define CP_WAIT2()  asm volatile("cp.async.wait_group 2;" ::: "memory")
#define CP_WAIT1()  asm volatile("cp.async.wait_group 1;" ::: "memory")
#define CP_WAIT0()  asm volatile("cp.async.wait_group 0;" ::: "memory")

__device__ __forceinline__ void ldsm_x4(uint32_t* r, uint32_t addr) {
    asm volatile("ldmatrix.sync.aligned.m8n8.x4.shared.b16 {%0,%1,%2,%3}, [%4];"
                 : "=r"(r[0]), "=r"(r[1]), "=r"(r[2]), "=r"(r[3]) : "r"(addr));
}
__device__ __forceinline__ void mma_f16(float* d, const uint32_t* a,
                                        uint32_t b0, uint32_t b1) {
    asm volatile(
        "mma.sync.aligned.m16n8k16.row.col.f32.f16.f16.f32 "
        "{%0,%1,%2,%3}, {%4,%5,%6,%7}, {%8,%9}, {%0,%1,%2,%3};"
        : "+f"(d[0]), "+f"(d[1]), "+f"(d[2]), "+f"(d[3])
        : "r"(a[0]), "r"(a[1]), "r"(a[2]), "r"(a[3]), "r"(b0), "r"(b1));
}

// ---------------------------------------------------------------------------
// fp32 -> fp16 convert, 8 elems/thread
// ---------------------------------------------------------------------------
__global__ __launch_bounds__(256) void cvt16_kernel(
    const float* __restrict__ src, uint16_t* __restrict__ dst, int n8)
{
    int i = blockIdx.x * blockDim.x + threadIdx.x;
    if (i >= n8) return;
    const float4* s4 = (const float4*)src;
    float4 a = s4[2 * i], b = s4[2 * i + 1];
    float v[8] = {a.x, a.y, a.z, a.w, b.x, b.y, b.z, b.w};
    uint32_t P[4];
    #pragma unroll
    for (int q = 0; q < 4; q++) {
        __half h0 = __float2half_rn(v[2 * q]);
        __half h1 = __float2half_rn(v[2 * q + 1]);
        P[q] = (uint32_t)__half_as_ushort(h0) | ((uint32_t)__half_as_ushort(h1) << 16);
    }
    *(uint4*)(dst + 8 * (size_t)i) = make_uint4(P[0], P[1], P[2], P[3]);
}

// ---------------------------------------------------------------------------
// Tensor-core gate GEMM via mma.sync (fp16 operands, fp32 accum).
// Tile 128x128x64, 256 threads, 3-stage cp.async pipeline (32KB/stage),
// SW128 smem, 2 CTAs/SM. Inner loop: 16 independent MMAs per k16 step.
// ---------------------------------------------------------------------------
#define STG_SZ  32768
#define OFF_B   16384

__device__ __forceinline__ void load_stage(uint32_t sb, int m0, int n0, size_t kof)
{
    const int tid = threadIdx.x;
    #pragma unroll
    for (int i = 0; i < 4; i++) {
        int idx = tid + 256 * i;
        int row = idx >> 3, ch = idx & 7;
        uint32_t sw = (uint32_t)((row * 128 + ch * 16) ^ ((row & 7) << 4));
        cp_async16(sb + sw,         g_A16 + (size_t)(m0 + row) * GK + kof + ch * 8);
        cp_async16(sb + OFF_B + sw, g_B16 + (size_t)(n0 + row) * GK + kof + ch * 8);
    }
}

__global__ __launch_bounds__(256, 2) void gate_mma_kernel(
    const float* __restrict__ bg, float* __restrict__ out)
{
    extern __shared__ char smem[];
    const uint32_t sbase = smem_u32(smem);

    const int tid  = threadIdx.x;
    const int lane = tid & 31;
    const int wid  = tid >> 5;
    const int wm   = wid & 3;          // warp m index (0-3) -> m offset wm*32
    const int wn   = wid >> 2;         // warp n index (0-1) -> n offset wn*64
    const int n0   = blockIdx.x * 128; // n fastest for L2 reuse of B
    const int m0   = blockIdx.y * 128;

    // per-lane ldmatrix address components (row&7 == lane&7 for all fragments)
    const uint32_t xorv = (uint32_t)((lane & 7) << 4);
    const uint32_t hi16 = (uint32_t)((lane >> 4) * 16);
    const uint32_t aRow = (uint32_t)((wm * 32 + (lane & 15)) * 128);
    const uint32_t bRow = (uint32_t)((wn * 64 + (lane & 15)) * 128);

    float d[2][8][4];
    #pragma unroll
    for (int mf = 0; mf < 2; mf++)
        #pragma unroll
        for (int nf = 0; nf < 8; nf++)
            #pragma unroll
            for (int q = 0; q < 4; q++) d[mf][nf][q] = 0.0f;

    load_stage(sbase,          m0, n0, 0);
    CP_COMMIT();
    load_stage(sbase + STG_SZ, m0, n0, BK);
    CP_COMMIT();

    uint32_t bufoff[3] = {0u, (uint32_t)STG_SZ, 2u * (uint32_t)STG_SZ};

    for (int c = 0; c < NCHUNK; c++) {
        if (c + 2 < NCHUNK) {
            load_stage(sbase + bufoff[(c + 2) % 3], m0, n0, (size_t)(c + 2) * BK);
            CP_COMMIT();
            CP_WAIT2();
        } else if (c + 1 < NCHUNK) {
            CP_WAIT1();
        } else {
            CP_WAIT0();
        }
        __syncthreads();

        const uint32_t sb = sbase + bufoff[c % 3];
        #pragma unroll
        for (int s = 0; s < 4; s++) {
            const uint32_t cb = ((uint32_t)(s * 32) + hi16) ^ xorv;
            uint32_t ah[2][4], bh[4][4];
            ldsm_x4(ah[0], sb + aRow + cb);
            ldsm_x4(ah[1], sb + aRow + 2048 + cb);
            #pragma unroll
            for (int g = 0; g < 4; g++)
                ldsm_x4(bh[g], sb + OFF_B + bRow + g * 2048 + cb);
            // B x4 reg mapping: nf even -> {r0, r2}, nf odd -> {r1, r3}.
            // 16 MMAs, all independent accumulators.
            #pragma unroll
            for (int mf = 0; mf < 2; mf++)
                #pragma unroll
                for (int nf = 0; nf < 8; nf++) {
                    const int g = nf >> 1, o = nf & 1;
                    mma_f16(d[mf][nf], ah[mf], bh[g][o], bh[g][o + 2]);
                }
        }
        __syncthreads();
    }

    // epilogue: bias + silu straight from fragments
    const int erow  = lane >> 2;
    const int ecol0 = (lane & 3) * 2;
    #pragma unroll
    for (int nf = 0; nf < 8; nf++) {
        const int col = n0 + wn * 64 + nf * 8 + ecol0;
        const float2 bgv = *(const float2*)(bg + col);
        #pragma unroll
        for (int mf = 0; mf < 2; mf++) {
            const int row = m0 + wm * 32 + mf * 16 + erow;
            float v0 = d[mf][nf][0] + bgv.x;
            float v1 = d[mf][nf][1] + bgv.y;
            float2 r0 = make_float2(v0 / (1.0f + expf(-v0)), v1 / (1.0f + expf(-v1)));
            *(float2*)(out + (size_t)row * GN + col) = r0;
            float v2 = d[mf][nf][2] + bgv.x;
            float v3 = d[mf][nf][3] + bgv.y;
            float2 r1 = make_float2(v2 / (1.0f + expf(-v2)), v3 / (1.0f + expf(-v3)));
            *(float2*)(out + (size_t)(row + 8) * GN + col) = r1;
        }
    }
}

// ---------------------------------------------------------------------------
// Monarch stage 1 over all samples: zx[s,k,i] = sum_j B1[k,i,j] * x[s, k*64+j]
// ---------------------------------------------------------------------------
__global__ __launch_bounds__(256) void monarch_s1_kernel(
    const float* __restrict__ B1, const float* __restrict__ vin)
{
    __shared__ float wT[64 * 68];
    __shared__ float xs[64 * 68];

    const int k  = blockIdx.x;
    const int s0 = blockIdx.y * 64;
    const int t  = threadIdx.x;
    const float* w = B1 + (size_t)k * 4096;

    #pragma unroll
    for (int r = 0; r < 16; r++) {
        int idx = t + 256 * r;
        int i = idx >> 6, j = idx & 63;
        wT[j * 68 + i] = w[idx];
    }
    {
        int sr = t >> 4, j4 = (t & 15) * 4;
        #pragma unroll
        for (int it = 0; it < 4; it++) {
            int s = sr + it * 16;
            float4 v = *(const float4*)(vin + (size_t)(s0 + s) * DIM + k * 64 + j4);
            *(float4*)(xs + s * 68 + j4) = v;
        }
    }
    __syncthreads();

    const int i0 = (t & 15) * 4;
    const int sg = t >> 4;
    float acc[4][4] = {};
    #pragma unroll 4
    for (int j = 0; j < 64; j++) {
        float4 w4 = *(const float4*)&wT[j * 68 + i0];
        #pragma unroll
        for (int q = 0; q < 4; q++) {
            float hv = xs[(sg * 4 + q) * 68 + j];
            acc[q][0] += w4.x * hv; acc[q][1] += w4.y * hv;
            acc[q][2] += w4.z * hv; acc[q][3] += w4.w * hv;
        }
    }
    #pragma unroll
    for (int q = 0; q < 4; q++) {
        int s = sg * 4 + q;
        *(float4*)(g_zx + (size_t)(s0 + s) * DIM + k * 64 + i0) =
            make_float4(acc[q][0], acc[q][1], acc[q][2], acc[q][3]);
    }
}

// ---------------------------------------------------------------------------
// Monarch stage 2: Mx[s, a*64+i] = sum_j B2[a,i,j] * zx[s, j*64 + a]
// ---------------------------------------------------------------------------
__global__ __launch_bounds__(256) void monarch_s2_kernel(
    const float* __restrict__ B2)
{
    __shared__ float wT[64 * 68];
    __shared__ float zs[64 * 68];

    const int a  = blockIdx.x;
    const int s0 = blockIdx.y * 64;
    const int t  = threadIdx.x;
    const float* w = B2 + (size_t)a * 4096;

    #pragma unroll
    for (int r = 0; r < 16; r++) {
        int idx = t + 256 * r;
        int i = idx >> 6, j = idx & 63;
        wT[j * 68 + i] = w[idx];
    }
    #pragma unroll
    for (int r = 0; r < 16; r++) {
        int idx = t + 256 * r;
        int s = idx >> 6, j = idx & 63;
        zs[s * 68 + j] = g_zx[(size_t)(s0 + s) * DIM + j * 64 + a];
    }
    __syncthreads();

    const int i0 = (t & 15) * 4;
    const int sg = t >> 4;
    float acc[4][4] = {};
    #pragma unroll 4
    for (int j = 0; j < 64; j++) {
        float4 w4 = *(const float4*)&wT[j * 68 + i0];
        #pragma unroll
        for (int q = 0; q < 4; q++) {
            float hv = zs[(sg * 4 + q) * 68 + j];
            acc[q][0] += w4.x * hv; acc[q][1] += w4.y * hv;
            acc[q][2] += w4.z * hv; acc[q][3] += w4.w * hv;
        }
    }
    #pragma unroll
    for (int q = 0; q < 4; q++) {
        int s = sg * 4 + q;
        *(float4*)(g_mx + (size_t)(s0 + s) * DIM + a * 64 + i0) =
            make_float4(acc[q][0], acc[q][1], acc[q][2], acc[q][3]);
    }
}

// ---------------------------------------------------------------------------
// Grid-wide sense barrier (release/acquire through L2). RCTA co-resident CTAs.
// ---------------------------------------------------------------------------
__device__ __forceinline__ void grid_barrier(unsigned target)
{
    __syncthreads();
    if (threadIdx.x == 0) {
        unsigned prev;
        asm volatile("atom.acq_rel.gpu.add.u32 %0, [%1], %2;"
                     : "=r"(prev) : "l"(&g_count), "r"(1u) : "memory");
        if (prev == RCTA - 1) {
            asm volatile("st.relaxed.gpu.u32 [%0], %1;" :: "l"(&g_count), "r"(0u) : "memory");
            asm volatile("red.release.gpu.add.u32 [%0], %1;" :: "l"(&g_gen), "r"(1u) : "memory");
        } else {
            unsigned v;
            do {
                asm volatile("ld.acquire.gpu.u32 %0, [%1];" : "=r"(v) : "l"(&g_gen) : "memory");
            } while ((int)(v - target) < 0);
        }
    }
    __syncthreads();
}

// ---------------------------------------------------------------------------
// Persistent recurrence kernel, 128 CTAs: CTA (c, half) owns monarch block c
// for batch rows [half*8, half*8+8). The all-to-all z shuffle stays within a
// half. FMA work spreads over 128 SMs.
// ---------------------------------------------------------------------------
__global__ __launch_bounds__(256) void recurrence_kernel(
    const float* __restrict__ B1, const float* __restrict__ B2,
    const float* __restrict__ h0, const float* __restrict__ bvec,
    float* __restrict__ out, float* __restrict__ hbuf)
{
    __shared__ float wT1[64 * 68];   // wT1[j*68+i] = B1[c][i][j]
    __shared__ float wT2[64 * 68];
    __shared__ float hs[8 * 68];     // h[b_local, c*64 + j]
    __shared__ float zs[8 * 68];     // z[b_local, j*64 + c]
    __shared__ unsigned s_base;

    const int c    = blockIdx.x & 63;
    const int half = blockIdx.x >> 6;
    const int tid  = threadIdx.x;
    const int bl   = tid >> 5;          // 0..7 local batch
    const int bgl  = half * 8 + bl;     // global batch row
    const int i0   = (tid & 31) * 2;    // 0..62

    if (tid == 0) {
        unsigned v;
        asm volatile("ld.acquire.gpu.u32 %0, [%1];" : "=r"(v) : "l"(&g_gen) : "memory");
        s_base = v;
    }

    #pragma unroll
    for (int r = 0; r < 16; r++) {
        int idx = tid + 256 * r;
        int i = idx >> 6, j = idx & 63;
        wT1[j * 68 + i] = B1[(size_t)c * 4096 + idx];
        wT2[j * 68 + i] = B2[(size_t)c * 4096 + idx];
    }
    {
        float2 v = *(const float2*)(h0 + (size_t)bgl * DIM + c * 64 + i0);
        *(float2*)&hs[bl * 68 + i0] = v;
        *(float2*)(hbuf + (size_t)bgl * DIM + c * 64 + i0) = v;   // h[0] output
    }
    const float2 bb = *(const float2*)(bvec + c * 64 + i0);
    __syncthreads();
    const unsigned base = s_base;

    for (int t = 0; t < T_STEPS; t++) {
        // ---- stage 1: z[b, c, i] = sum_j W1[c][i][j] * h[b, c*64+j] ----
        float ax = 0.f, ay = 0.f;
        #pragma unroll 8
        for (int j = 0; j < 64; j++) {
            float2 w2 = *(const float2*)&wT1[j * 68 + i0];
            float hv = hs[bl * 68 + j];
            ax += w2.x * hv; ay += w2.y * hv;
        }
        float* zb = g_zbuf + (size_t)(t & 1) * BD;
        *(float2*)(zb + (size_t)bgl * DIM + c * 64 + i0) = make_float2(ax, ay);

        grid_barrier(base + (unsigned)t + 1u);

        // ---- gather shuffled z: zs[b2][j] = z[half*8+b2, j*64 + c] ----
        #pragma unroll
        for (int r = 0; r < 2; r++) {
            int idx = tid + 256 * r;
            int b2 = idx >> 6, j = idx & 63;
            zs[b2 * 68 + j] = zb[(size_t)(half * 8 + b2) * DIM + j * 64 + c];
        }
        __syncthreads();

        // ---- stage 2 + tanh + gating ----
        float cx = 0.f, cy = 0.f;
        #pragma unroll 8
        for (int j = 0; j < 64; j++) {
            float2 w2 = *(const float2*)&wT2[j * 68 + i0];
            float zv = zs[bl * 68 + j];
            cx += w2.x * zv; cy += w2.y * zv;
        }

        const size_t base_idx = (size_t)bgl * DIM + c * 64 + i0;
        float2 mx2 = *(const float2*)(g_mx + (size_t)t * BD + base_idx);
        float2 gg  = *(const float2*)(out + (size_t)t * BD + base_idx);  // gate

        float h0v = tanhf(cx + mx2.x + bb.x);
        float h1v = tanhf(cy + mx2.y + bb.y);

        *(float2*)(hbuf + (size_t)(t + 1) * BD + base_idx) = make_float2(h0v, h1v);
        *(float2*)(out + (size_t)t * BD + base_idx) =
            make_float2(h0v * gg.x, h1v * gg.y);

        // update local h slice for next step's stage 1 (safe: all stage-1 reads
        // of hs finished before the grid barrier above)
        *(float2*)&hs[bl * 68 + i0] = make_float2(h0v, h1v);
        __syncthreads();
    }
}

// ---------------------------------------------------------------------------
// Inputs (metadata order): x, h0, B1_h, B2_h, B1_x, B2_x, W_gate, b, b_gate
// Output: [ output (T,B,D) | h (T+1,B,D) ] float32
// ---------------------------------------------------------------------------
extern "C" void kernel_launch(void* const* d_in, const int* in_sizes, int n_in,
                              void* d_out, int out_size)
{
    const float* x    = (const float*)d_in[0];
    const float* h0   = (const float*)d_in[1];
    const float* B1h  = (const float*)d_in[2];
    const float* B2h  = (const float*)d_in[3];
    const float* B1x  = (const float*)d_in[4];
    const float* B2x  = (const float*)d_in[5];
    const float* Wg   = (const float*)d_in[6];
    const float* bvec = (const float*)d_in[7];
    const float* bg   = (const float*)d_in[8];

    float* out  = (float*)d_out;                       // [T, B, D]
    float* hbuf = out + (size_t)T_STEPS * BD;          // [T+1, B, D]

    uint16_t *pA16, *pB16;
    cudaGetSymbolAddress((void**)&pA16, g_A16);
    cudaGetSymbolAddress((void**)&pB16, g_B16);

    // fp16 conversion of x and W_gate
    cvt16_kernel<<<(GM * (GK / 8)) / 256, 256>>>(x, pA16, GM * GK / 8);
    cvt16_kernel<<<(GN * (GK / 8)) / 256, 256>>>(Wg, pB16, GN * GK / 8);

    // tensor-core gate GEMM (fp16 mma.sync) -> gate stored into output region
    static const int SMEM_SZ = 3 * STG_SZ;   // 96 KB (2 CTAs/SM)
    cudaFuncSetAttribute(gate_mma_kernel, cudaFuncAttributeMaxDynamicSharedMemorySize, SMEM_SZ);
    gate_mma_kernel<<<dim3(GN / 128, GM / 128), 256, SMEM_SZ>>>(bg, out);

    // Mx = monarch(B1_x, B2_x, x) for all timesteps
    monarch_s1_kernel<<<dim3(64, S_TOT / 64), 256>>>(B1x, x);
    monarch_s2_kernel<<<dim3(64, S_TOT / 64), 256>>>(B2x);

    // Entire 512-step recurrence in ONE persistent kernel (128 CTAs)
    recurrence_kernel<<<RCTA, 256>>>(B1h, B2h, h0, bvec, out, hbuf);
}